// round 1
// baseline (speedup 1.0000x reference)
#include <cuda_runtime.h>
#include <cstdint>

// out[s,b,d] = x[s,b,d] + ((S-1)*0.5f - s)
// S=4096, B=4, D=2048  ->  33,554,432 fp32 elements.
// Pure HBM stream: 268 MB total traffic. float4 vectorized.
//
// Linear float4 index i4 covers 4 contiguous d-elements (D divisible by 4),
// so all 4 share the same s. Elements-per-s = B*D = 8192 -> float4s per s = 2048.
// s = i4 >> 11.

__global__ void relpos_add_kernel(const float4* __restrict__ x,
                                  float4* __restrict__ out,
                                  int n4, float half_sm1) {
    int i = blockIdx.x * blockDim.x + threadIdx.x;
    if (i >= n4) return;
    int s = i >> 11;                      // (B*D)/4 = 2048 float4 per s
    float bias = half_sm1 - (float)s;     // (S-1)/2 - s
    float4 v = x[i];
    v.x += bias;
    v.y += bias;
    v.z += bias;
    v.w += bias;
    out[i] = v;
}

extern "C" void kernel_launch(void* const* d_in, const int* in_sizes, int n_in,
                              void* d_out, int out_size) {
    const float4* x = (const float4*)d_in[0];
    float4* out = (float4*)d_out;

    const int total = in_sizes[0];        // 33,554,432
    const int n4 = total / 4;             // 8,388,608
    // seq_len = 4096 (total / (B*D) = total / 8192)
    const int seq_len = total / 8192;
    const float half_sm1 = 0.5f * (float)(seq_len - 1);

    const int threads = 256;
    const int blocks = (n4 + threads - 1) / threads;
    relpos_add_kernel<<<blocks, threads>>>(x, out, n4, half_sm1);
}

// round 2
// speedup vs baseline: 1.0324x; 1.0324x over previous
#include <cuda_runtime.h>
#include <cstdint>

// out[s,b,d] = x[s,b,d] + ((S-1)*0.5f - s)
// Pure HBM stream, 268 MB. float4 x 4 per thread for MLP=4,
// streaming cache hints (.cs) since there is zero reuse.
//
// float4s per s = B*D/4 = 2048, so s = i4 >> 11.

#define V_PER_THREAD 4

__global__ void relpos_add_kernel(const float4* __restrict__ x,
                                  float4* __restrict__ out,
                                  int n4, float half_sm1) {
    int base = (blockIdx.x * blockDim.x) * V_PER_THREAD + threadIdx.x;

    int idx[V_PER_THREAD];
    float4 v[V_PER_THREAD];

    // Front-batched independent loads -> MLP = 4
    #pragma unroll
    for (int k = 0; k < V_PER_THREAD; k++) {
        idx[k] = base + k * blockDim.x;
        if (idx[k] < n4) v[k] = __ldcs(&x[idx[k]]);
    }

    #pragma unroll
    for (int k = 0; k < V_PER_THREAD; k++) {
        if (idx[k] < n4) {
            float bias = half_sm1 - (float)(idx[k] >> 11);
            v[k].x += bias;
            v[k].y += bias;
            v[k].z += bias;
            v[k].w += bias;
            __stcs(&out[idx[k]], v[k]);
        }
    }
}

extern "C" void kernel_launch(void* const* d_in, const int* in_sizes, int n_in,
                              void* d_out, int out_size) {
    const float4* x = (const float4*)d_in[0];
    float4* out = (float4*)d_out;

    const int total = in_sizes[0];        // 33,554,432
    const int n4 = total / 4;             // 8,388,608
    const int seq_len = total / 8192;     // 4096
    const float half_sm1 = 0.5f * (float)(seq_len - 1);

    const int threads = 256;
    const int elems_per_block = threads * V_PER_THREAD;
    const int blocks = (n4 + elems_per_block - 1) / elems_per_block;  // 8192
    relpos_add_kernel<<<blocks, threads>>>(x, out, n4, half_sm1);
}